// round 11
// baseline (speedup 1.0000x reference)
#include <cuda_runtime.h>
#include <cuda_bf16.h>
#include <math.h>

// Attention path collapses (softmax rows sum to 1; T,S fully contracted):
//   y = 1024 * (h_pred @ Wv + bv)
// Only Wv/Wo projection + gate MLP + mixer MLP survive.
//
// R10: 2 CTAs per SM. ROWS=4, grid=256, 24KB smem/CTA, <=64 regs via
// __launch_bounds__(512,2). Two independent barrier domains per SM so one
// CTA's barrier/reduce stalls are hidden by the other's GEMM warps.
// Keeps R9's merged phase graph {S1,S3}->{S2,S4}->{S5}->{S6}, 1-line LDG
// weight pattern (32-deep), broadcast LDS.128 activations, hoisted biases.

#define HID 128
#define ROWS 4
#define SLICES 4
#define KS 32                    // k-values per slice
#define NNODES 1024
#define NTHREADS 512

typedef unsigned long long u64;

__device__ __forceinline__ u64 fma2(u64 a, u64 b, u64 c) {
    u64 d;
    asm("fma.rn.f32x2 %0, %1, %2, %3;" : "=l"(d) : "l"(a), "l"(b), "l"(c));
    return d;
}

__device__ __forceinline__ void load32(const float* __restrict__ W, int c,
                                       int k, float w[32]) {
#pragma unroll
    for (int i = 0; i < 32; i++) w[i] = W[(k + i) * HID + c];
}

// 32 k-steps: one broadcast LDS.128 per k (4 rows), weights in registers.
__device__ __forceinline__ void fma32(const float* __restrict__ act, int k,
                                      const float w[32], u64 acc[2]) {
#pragma unroll
    for (int i = 0; i < 32; i++) {
        u64 ww;
        asm("mov.b64 %0, {%1, %1};" : "=l"(ww) : "f"(w[i]));
        ulonglong2 av = *(const ulonglong2*)(act + (k + i) * ROWS);
        acc[0] = fma2(av.x, ww, acc[0]);   // rows 0,1
        acc[1] = fma2(av.y, ww, acc[1]);   // rows 2,3
    }
}

extern "C" __global__ void __launch_bounds__(NTHREADS, 2)
temporal_attn_fused(const float* __restrict__ h_prev,
                    const float* __restrict__ h_pred,
                    const float* __restrict__ Wv, const float* __restrict__ bv,
                    const float* __restrict__ Wo, const float* __restrict__ bo,
                    const float* __restrict__ gW1, const float* __restrict__ gb1,
                    const float* __restrict__ gW2, const float* __restrict__ gb2,
                    const float* __restrict__ mW1, const float* __restrict__ mb1,
                    const float* __restrict__ mW2, const float* __restrict__ mb2,
                    float* __restrict__ out) {
    __shared__ float bufA[HID * ROWS];         // 2KB  h_pred, later h_corr
    __shared__ float hvF[HID * ROWS];          // 2KB  h_prev
    __shared__ float bufC[HID * ROWS];         // 2KB  v, later m1
    __shared__ float g1F[HID * ROWS];          // 2KB  gate hidden
    __shared__ float pA[SLICES * HID * ROWS];  // 8KB  partials A
    __shared__ float pB[SLICES * HID * ROWS];  // 8KB  partials B

    const int tid = threadIdx.x;
    const int c = tid & (HID - 1);   // output column (GEMM phase)
    const int s = tid >> 7;          // k-slice 0..3 (warp-uniform)
    const int k0 = s * KS;
    const int r0 = blockIdx.x * ROWS;
    const int p = tid;               // element owned in reduce phases
    const int q = p >> 2;            // its column index (ROWS=4)

    // Hoisted bias loads (off the post-barrier critical paths).
    const float bv_r  = bv[q],  bo_r  = bo[q];
    const float gb1_r = gb1[q], gb2_r = gb2[q];
    const float mb1_r = mb1[q], mb2_r = mb2[q];

    float w[32];
    load32(Wv, c, k0, w);            // P1/S1 weights, in flight during staging

    // Stage input tiles transposed: [k][r], coalesced global reads.
    {
        int r = tid >> 7, cc = tid & (HID - 1);
        bufA[cc * ROWS + r] = h_pred[(r0 + r) * HID + cc];
        hvF[cc * ROWS + r]  = h_prev[(r0 + r) * HID + cc];
    }
    __syncthreads();                              // bar0

    u64 acc[2];
    float* pAdst = pA + s * 512 + c * ROWS;
    float* pBdst = pB + s * 512 + c * ROWS;

#define GEMM_ZERO() { acc[0] = acc[1] = 0ULL; }
#define PSTORE(dst) { *(ulonglong2*)(dst) = make_ulonglong2(acc[0], acc[1]); }
#define RED4A(x) float x = (pA[p] + pA[512 + p]) + (pA[1024 + p] + pA[1536 + p])
#define RED4B(x) float x = (pB[p] + pB[512 + p]) + (pB[1024 + p] + pB[1536 + p])

    float outv, hcv;
    const float* Wm = (s < 2) ? Wo : gW2;      // P2 merged-stage matrix
    const int k0m = (s & 1) * 64;              // P2 merged-stage k-offset

    // ======== P1: S1 (v = hp@Wv) -> pA ; S3 (gate hidden pre-act) -> pB ====
    GEMM_ZERO();
    fma32(bufA, k0, w, acc);
    load32(gW1, c, k0, w);                     // S3 top half
    PSTORE(pAdst);
    GEMM_ZERO();
    fma32(bufA, k0, w, acc);
    load32(gW1 + HID * HID, c, k0, w);         // S3 bottom half
    fma32(hvF, k0, w, acc);
    load32(Wm, c, k0m, w);                     // prefetch P2 chunk0
    PSTORE(pBdst);
    __syncthreads();                              // bar1
    {
        RED4A(v); bufC[p] = v + bv_r;
        RED4B(x); x += gb1_r; g1F[p] = x / (1.0f + __expf(-x));
    }
    __syncthreads();                              // bar2

    // ======== P2: merged S2+S4 — slices 0-1: v@Wo, slices 2-3: g1@gW2 ======
    {
        const float* actm = (s < 2) ? bufC : g1F;
        GEMM_ZERO();
        fma32(actm, k0m, w, acc);
        load32(Wm, c, k0m + 32, w);            // second 32-k chunk
        fma32(actm, k0m + 32, w, acc);
        load32(mW1, c, k0, w);                 // prefetch P3 top half
        PSTORE(pAdst);
    }
    __syncthreads();                              // bar3
    {
        float v = pA[p] + pA[512 + p];               // S2 partials (slices 0-1)
        outv = (float)NNODES * v + bo_r;
        float x = pA[1024 + p] + pA[1536 + p];       // S4 partials (slices 2-3)
        x += gb2_r;
        float g = 1.0f / (1.0f + __expf(-x));
        hcv = hvF[p] + g * outv;
        bufA[p] = hcv;                               // h_corr (h_pred dead)
    }
    __syncthreads();                              // bar4

    // ======== P3: S5 m1 = relu(hc@mW1_top + hv@mW1_bot + mb1) -> bufC ======
    GEMM_ZERO();
    fma32(bufA, k0, w, acc);
    load32(mW1 + HID * HID, c, k0, w);         // S5 bottom half
    fma32(hvF, k0, w, acc);
    load32(mW2, c, k0, w);                     // prefetch P4
    PSTORE(pAdst);
    __syncthreads();                              // bar5
    {
        RED4A(x); bufC[p] = fmaxf(x + mb1_r, 0.0f);
    }
    __syncthreads();                              // bar6

    // ======== P4: S6 mixed = h_corr + m1@mW2 + mb2 -> global ========
    GEMM_ZERO();
    fma32(bufC, k0, w, acc);
    PSTORE(pAdst);
    __syncthreads();                              // bar7
    {
        RED4A(v);
        out[(r0 + (p & 3)) * HID + q] = hcv + v + mb2_r;
    }
}

extern "C" void kernel_launch(void* const* d_in, const int* in_sizes, int n_in,
                              void* d_out, int out_size) {
    // metadata order: h_prev, h_pred, adj_rows, adj_cols, Wq, bq, Wk, bk,
    //                 Wv, bv, Wo, bo, gW1, gb1, gW2, gb2, mW1, mb1, mW2, mb2
    const float* h_prev = (const float*)d_in[0];
    const float* h_pred = (const float*)d_in[1];
    // d_in[2..7] (adjacency, Wq/bq/Wk/bk) are algebraically dead.
    const float* Wv  = (const float*)d_in[8];
    const float* bv  = (const float*)d_in[9];
    const float* Wo  = (const float*)d_in[10];
    const float* bo  = (const float*)d_in[11];
    const float* gW1 = (const float*)d_in[12];
    const float* gb1 = (const float*)d_in[13];
    const float* gW2 = (const float*)d_in[14];
    const float* gb2 = (const float*)d_in[15];
    const float* mW1 = (const float*)d_in[16];
    const float* mb1 = (const float*)d_in[17];
    const float* mW2 = (const float*)d_in[18];
    const float* mb2 = (const float*)d_in[19];
    float* out = (float*)d_out;

    temporal_attn_fused<<<NNODES / ROWS, NTHREADS>>>(
        h_prev, h_pred, Wv, bv, Wo, bo,
        gW1, gb1, gW2, gb2, mW1, mb1, mW2, mb2, out);
}

// round 12
// speedup vs baseline: 1.1065x; 1.1065x over previous
#include <cuda_runtime.h>
#include <cuda_bf16.h>
#include <math.h>

// Attention path collapses (softmax rows sum to 1; T,S fully contracted):
//   y = 1024 * (h_pred @ Wv + bv)
// Only Wv/Wo projection + gate MLP + mixer MLP survive.
//
// R11: LSU-throughput fix. 2 output columns per thread (c, c+64) x 8
// k-slices: the two broadcast LDS.128 activation loads per k now feed 8
// FFMA2 instead of 4, cutting LSU ops/FFMA2 from 0.75 to 0.5 (~-30% LSU
// ops/thread). Warp-uniform slices (s = wid>>1), 1-line weight LDGs,
// single 32KB partial buffer, 48KB static smem, merged S2+S4.

#define HID 128
#define ROWS 8
#define SLICES 8
#define NNODES 1024
#define NTHREADS 512

typedef unsigned long long u64;

__device__ __forceinline__ u64 fma2(u64 a, u64 b, u64 c) {
    u64 d;
    asm("fma.rn.f32x2 %0, %1, %2, %3;" : "=l"(d) : "l"(a), "l"(b), "l"(c));
    return d;
}

// Load 8 k-steps of weights for both owned columns.
__device__ __forceinline__ void loadW(const float* __restrict__ W, int c0,
                                      int c1, int k, float w0[8], float w1[8]) {
#pragma unroll
    for (int i = 0; i < 8; i++) {
        w0[i] = W[(k + i) * HID + c0];
        w1[i] = W[(k + i) * HID + c1];
    }
}

// 8 k-steps: two broadcast LDS.128 per k serve 8 FFMA2 (8 rows x 2 cols).
__device__ __forceinline__ void fma8(const float* __restrict__ act, int k,
                                     const float w0[8], const float w1[8],
                                     u64 acc[8]) {
#pragma unroll
    for (int i = 0; i < 8; i++) {
        u64 ww0, ww1;
        asm("mov.b64 %0, {%1, %1};" : "=l"(ww0) : "f"(w0[i]));
        asm("mov.b64 %0, {%1, %1};" : "=l"(ww1) : "f"(w1[i]));
        const ulonglong2* a = (const ulonglong2*)(act + (k + i) * ROWS);
        ulonglong2 a01 = a[0];   // rows 0..3
        ulonglong2 a23 = a[1];   // rows 4..7
        acc[0] = fma2(a01.x, ww0, acc[0]);
        acc[1] = fma2(a01.y, ww0, acc[1]);
        acc[2] = fma2(a23.x, ww0, acc[2]);
        acc[3] = fma2(a23.y, ww0, acc[3]);
        acc[4] = fma2(a01.x, ww1, acc[4]);
        acc[5] = fma2(a01.y, ww1, acc[5]);
        acc[6] = fma2(a23.x, ww1, acc[6]);
        acc[7] = fma2(a23.y, ww1, acc[7]);
    }
}

__device__ __forceinline__ void part_store(float* d0, float* d1,
                                           const u64 acc[8]) {
    ((ulonglong2*)d0)[0] = make_ulonglong2(acc[0], acc[1]);
    ((ulonglong2*)d0)[1] = make_ulonglong2(acc[2], acc[3]);
    ((ulonglong2*)d1)[0] = make_ulonglong2(acc[4], acc[5]);
    ((ulonglong2*)d1)[1] = make_ulonglong2(acc[6], acc[7]);
}

extern "C" __global__ void __launch_bounds__(NTHREADS, 1)
temporal_attn_fused(const float* __restrict__ h_prev,
                    const float* __restrict__ h_pred,
                    const float* __restrict__ Wv, const float* __restrict__ bv,
                    const float* __restrict__ Wo, const float* __restrict__ bo,
                    const float* __restrict__ gW1, const float* __restrict__ gb1,
                    const float* __restrict__ gW2, const float* __restrict__ gb2,
                    const float* __restrict__ mW1, const float* __restrict__ mb1,
                    const float* __restrict__ mW2, const float* __restrict__ mb2,
                    float* __restrict__ out) {
    __shared__ float bufA[HID * ROWS];          // 4KB  h_pred, later h_corr
    __shared__ float hvF[HID * ROWS];           // 4KB  h_prev
    __shared__ float bufC[HID * ROWS];          // 4KB  v, later m1
    __shared__ float g1F[HID * ROWS];           // 4KB  gate hidden
    __shared__ float pA[SLICES * HID * ROWS];   // 32KB partials

    const int tid = threadIdx.x;
    const int lane = tid & 31;
    const int wid = tid >> 5;
    const int s = wid >> 1;                 // k-slice 0..7 (warp-uniform)
    const int c0 = (wid & 1) * 32 + lane;   // first owned column (0..63)
    const int c1 = c0 + 64;                 // second owned column
    const int k0 = s * 16;
    const int r0 = blockIdx.x * ROWS;
    const int p0 = tid, p1 = tid + NTHREADS;   // elements owned in reduces
    const int q0 = p0 >> 3, q1 = p1 >> 3;      // their column indices

    // Hoisted bias loads (off the post-barrier critical paths).
    const float bv0 = bv[q0], bv1 = bv[q1];
    const float bo0 = bo[q0], bo1 = bo[q1];
    const float gb10 = gb1[q0], gb11 = gb1[q1];
    const float gb20 = gb2[q0], gb21 = gb2[q1];
    const float mb10 = mb1[q0], mb11 = mb1[q1];
    const float mb20 = mb2[q0], mb21 = mb2[q1];

    float wp0[8], wp1[8], wt0[8], wt1[8];
    loadW(Wv, c0, c1, k0, wp0, wp1);        // S1 chunk0, in flight now

    // Stage input tiles transposed: [k][r], coalesced global reads.
#pragma unroll
    for (int j = 0; j < 2; j++) {
        int g = tid + j * NTHREADS;
        int r = g >> 7, cc = g & (HID - 1);
        bufA[cc * ROWS + r] = h_pred[(r0 + r) * HID + cc];
        hvF[cc * ROWS + r]  = h_prev[(r0 + r) * HID + cc];
    }
    __syncthreads();                              // bar0

    u64 acc[8];
    float* pD0 = pA + s * 1024 + c0 * ROWS;
    float* pD1 = pA + s * 1024 + c1 * ROWS;

#define GEMM_ZERO() { acc[0]=acc[1]=acc[2]=acc[3]=acc[4]=acc[5]=acc[6]=acc[7]=0ULL; }
#define RED8(x, p)  float x = ((pA[p] + pA[1024 + (p)]) + (pA[2048 + (p)] + pA[3072 + (p)])) \
                            + ((pA[4096 + (p)] + pA[5120 + (p)]) + (pA[6144 + (p)] + pA[7168 + (p)]))

    float outv0, outv1, hcv0, hcv1;
    const float* Wm = (s < 4) ? Wo : gW2;      // merged-stage matrix
    const int k0m = (s & 3) * 32;              // merged-stage k-offset

    // ---- S1: v = h_pred @ Wv + bv -> bufC ----
    GEMM_ZERO();
    loadW(Wv, c0, c1, k0 + 8, wt0, wt1);
    fma8(bufA, k0, wp0, wp1, acc);
    loadW(gW1, c0, c1, k0, wp0, wp1);          // prefetch S3 chunk0
    fma8(bufA, k0 + 8, wt0, wt1, acc);
    part_store(pD0, pD1, acc);
    __syncthreads();                              // bar1
    { RED8(v0, p0); bufC[p0] = v0 + bv0; RED8(v1, p1); bufC[p1] = v1 + bv1; }
    __syncthreads();                              // bar2

    // ---- S3: g1 = silu(h_pred@gW1_top + h_prev@gW1_bot + gb1) -> g1F ----
    GEMM_ZERO();
    loadW(gW1, c0, c1, k0 + 8, wt0, wt1);
    fma8(bufA, k0, wp0, wp1, acc);
    loadW(gW1 + HID * HID, c0, c1, k0, wp0, wp1);
    fma8(bufA, k0 + 8, wt0, wt1, acc);
    loadW(gW1 + HID * HID, c0, c1, k0 + 8, wt0, wt1);
    fma8(hvF, k0, wp0, wp1, acc);
    loadW(Wm, c0, c1, k0m, wp0, wp1);          // prefetch P2 chunk0
    fma8(hvF, k0 + 8, wt0, wt1, acc);
    part_store(pD0, pD1, acc);
    __syncthreads();                              // bar3
    {
        RED8(x0, p0); x0 += gb10; g1F[p0] = x0 / (1.0f + __expf(-x0));
        RED8(x1, p1); x1 += gb11; g1F[p1] = x1 / (1.0f + __expf(-x1));
    }
    __syncthreads();                              // bar4

    // ---- P2 merged: slices 0-3 do v@Wo, slices 4-7 do g1@gW2 (32 k each) ----
    {
        const float* actm = (s < 4) ? bufC : g1F;
        GEMM_ZERO();
        loadW(Wm, c0, c1, k0m + 8, wt0, wt1);
        fma8(actm, k0m, wp0, wp1, acc);
        loadW(Wm, c0, c1, k0m + 16, wp0, wp1);
        fma8(actm, k0m + 8, wt0, wt1, acc);
        loadW(Wm, c0, c1, k0m + 24, wt0, wt1);
        fma8(actm, k0m + 16, wp0, wp1, acc);
        loadW(mW1, c0, c1, k0, wp0, wp1);      // prefetch S5 chunk0
        fma8(actm, k0m + 24, wt0, wt1, acc);
        part_store(pD0, pD1, acc);
    }
    __syncthreads();                              // bar5
    {
        float v0 = (pA[p0] + pA[1024 + p0]) + (pA[2048 + p0] + pA[3072 + p0]);
        float v1 = (pA[p1] + pA[1024 + p1]) + (pA[2048 + p1] + pA[3072 + p1]);
        outv0 = (float)NNODES * v0 + bo0;
        outv1 = (float)NNODES * v1 + bo1;
        float x0 = (pA[4096 + p0] + pA[5120 + p0]) + (pA[6144 + p0] + pA[7168 + p0]);
        float x1 = (pA[4096 + p1] + pA[5120 + p1]) + (pA[6144 + p1] + pA[7168 + p1]);
        x0 += gb20; x1 += gb21;
        float g0 = 1.0f / (1.0f + __expf(-x0));
        float g1 = 1.0f / (1.0f + __expf(-x1));
        hcv0 = hvF[p0] + g0 * outv0;
        hcv1 = hvF[p1] + g1 * outv1;
        bufA[p0] = hcv0;                          // h_corr (h_pred dead)
        bufA[p1] = hcv1;
    }
    __syncthreads();                              // bar6

    // ---- S5: m1 = relu(h_corr@mW1_top + h_prev@mW1_bot + mb1) -> bufC ----
    GEMM_ZERO();
    loadW(mW1, c0, c1, k0 + 8, wt0, wt1);
    fma8(bufA, k0, wp0, wp1, acc);
    loadW(mW1 + HID * HID, c0, c1, k0, wp0, wp1);
    fma8(bufA, k0 + 8, wt0, wt1, acc);
    loadW(mW1 + HID * HID, c0, c1, k0 + 8, wt0, wt1);
    fma8(hvF, k0, wp0, wp1, acc);
    loadW(mW2, c0, c1, k0, wp0, wp1);          // prefetch S6 chunk0
    fma8(hvF, k0 + 8, wt0, wt1, acc);
    part_store(pD0, pD1, acc);
    __syncthreads();                              // bar7
    {
        RED8(x0, p0); bufC[p0] = fmaxf(x0 + mb10, 0.0f);
        RED8(x1, p1); bufC[p1] = fmaxf(x1 + mb11, 0.0f);
    }
    __syncthreads();                              // bar8

    // ---- S6: mixed = h_corr + m1 @ mW2 + mb2 -> global ----
    GEMM_ZERO();
    loadW(mW2, c0, c1, k0 + 8, wt0, wt1);
    fma8(bufC, k0, wp0, wp1, acc);
    fma8(bufC, k0 + 8, wt0, wt1, acc);
    part_store(pD0, pD1, acc);
    __syncthreads();                              // bar9
    {
        RED8(v0, p0);
        out[(r0 + (p0 & 7)) * HID + q0] = hcv0 + v0 + mb20;
        RED8(v1, p1);
        out[(r0 + (p1 & 7)) * HID + q1] = hcv1 + v1 + mb21;
    }
}

extern "C" void kernel_launch(void* const* d_in, const int* in_sizes, int n_in,
                              void* d_out, int out_size) {
    // metadata order: h_prev, h_pred, adj_rows, adj_cols, Wq, bq, Wk, bk,
    //                 Wv, bv, Wo, bo, gW1, gb1, gW2, gb2, mW1, mb1, mW2, mb2
    const float* h_prev = (const float*)d_in[0];
    const float* h_pred = (const float*)d_in[1];
    // d_in[2..7] (adjacency, Wq/bq/Wk/bk) are algebraically dead.
    const float* Wv  = (const float*)d_in[8];
    const float* bv  = (const float*)d_in[9];
    const float* Wo  = (const float*)d_in[10];
    const float* bo  = (const float*)d_in[11];
    const float* gW1 = (const float*)d_in[12];
    const float* gb1 = (const float*)d_in[13];
    const float* gW2 = (const float*)d_in[14];
    const float* gb2 = (const float*)d_in[15];
    const float* mW1 = (const float*)d_in[16];
    const float* mb1 = (const float*)d_in[17];
    const float* mW2 = (const float*)d_in[18];
    const float* mb2 = (const float*)d_in[19];
    float* out = (float*)d_out;

    temporal_attn_fused<<<NNODES / ROWS, NTHREADS>>>(
        h_prev, h_pred, Wv, bv, Wo, bo,
        gW1, gb1, gW2, gb2, mW1, mb1, mW2, mb2, out);
}